// round 17
// baseline (speedup 1.0000x reference)
#include <cuda_runtime.h>
#include <cuda_fp16.h>
#include <math.h>
#include <stdint.h>

#define LDIM 96
#define FDIM 192
#define TILE_R 128
#define NTHREADS 256     // 8 warps = 2 m-halves (64 rows, 4 m16-blocks) x 4 n-quarters

// pitches conflict-free: P96 = 208 B (k=96), P192 = 400 B (k=192)
#define P96   208
#define P192  400
#define OFF_B1H 0                      // M1 hi: 192 n x 96 k fp16 (39,936)
#define OFF_B1L 39936
#define OFF_B2H 79872                  // W2^T hi: 96 n x 192 k fp16 (38,400)
#define OFF_B2L 118272
#define OFF_XH  156672                 // X hi: 128 x 96 fp16 (26,624)  [aliases H]
#define OFF_HH  156672                 // H hi: 128 x 192 fp16 (51,200)
#define OFF_S   207872                 // 4 x 128 f32 (2,048)
#define OFF_Q   209920                 // 4 x 128 f32 (2,048)
#define OFF_GAM 211968                 // 96 f32
#define OFF_BET 212352                 // 96 f32
#define SMEM_BYTES 212736

// Folded DCT * W1 (96 x 192), fp64 accumulation, recomputed every launch.
__device__ float g_M1[LDIM * FDIM];

__global__ void precompute_m1_kernel(const float* __restrict__ W1) {
    __shared__ double ct[LDIM];
    int n = blockIdx.x;
    int j = threadIdx.x;
    if (j < LDIM) {
        double base = 3.14159265358979323846 * (2.0 * (double)n + 1.0) / (2.0 * (double)LDIM);
        ct[j] = 2.0 * cos(base * (double)j);
    }
    __syncthreads();
    double acc = 0.0;
    for (int f = 0; f < LDIM; ++f)
        acc += ct[f] * (double)W1[f * FDIM + j];
    g_M1[n * FDIM + j] = (float)acc;
}

__device__ __forceinline__ void mma_f16(float* c, uint32_t a0, uint32_t a1,
                                        uint32_t a2, uint32_t a3,
                                        uint32_t b0, uint32_t b1) {
    asm volatile(
        "mma.sync.aligned.m16n8k16.row.col.f32.f16.f16.f32 "
        "{%0,%1,%2,%3}, {%4,%5,%6,%7}, {%8,%9}, {%0,%1,%2,%3};"
        : "+f"(c[0]), "+f"(c[1]), "+f"(c[2]), "+f"(c[3])
        : "r"(a0), "r"(a1), "r"(a2), "r"(a3), "r"(b0), "r"(b1));
}

__device__ __forceinline__ void split1(float v, uint16_t& h, uint16_t& l) {
    __half hb = __float2half_rn(v);
    __half lb = __float2half_rn(v - __half2float(hb));
    h = __half_as_ushort(hb);
    l = __half_as_ushort(lb);
}
__device__ __forceinline__ uint16_t h16(float v) {
    return __half_as_ushort(__float2half_rn(v));
}
__device__ __forceinline__ uint32_t pack2(uint16_t lo, uint16_t hi) {
    return (uint32_t)lo | ((uint32_t)hi << 16);
}

__global__ void __launch_bounds__(NTHREADS, 1)
fused_mma_kernel(const float* __restrict__ x,
                 const float* __restrict__ W2,
                 const float* __restrict__ gamma,
                 const float* __restrict__ beta,
                 float* __restrict__ out,
                 int ntiles)
{
    extern __shared__ char sm[];
    float* S   = (float*)(sm + OFF_S);
    float* Q   = (float*)(sm + OFF_Q);
    float* GAM = (float*)(sm + OFF_GAM);
    float* BET = (float*)(sm + OFF_BET);

    const int tid  = threadIdx.x;
    const int lane = tid & 31;
    const int wid  = tid >> 5;         // 0..7
    const int mh   = wid & 1;          // m-half: rows mh*64 .. mh*64+63 (4 m16 blocks)
    const int nq   = wid >> 1;         // n-quarter 0..3
    const int g    = lane >> 2;        // 0..7
    const int t    = lane & 3;         // 0..3

    // ---- one-time weight prep: fp16 hi/lo, conflict-free pitches ----
    for (int i = tid; i < LDIM * FDIM; i += NTHREADS) {      // B1[n][k] = M1[k][n]
        int k = i / FDIM, n = i - k * FDIM;
        uint16_t h, l; split1(g_M1[i], h, l);
        *(uint16_t*)(sm + OFF_B1H + n * P96 + k * 2) = h;
        *(uint16_t*)(sm + OFF_B1L + n * P96 + k * 2) = l;
    }
    for (int i = tid; i < FDIM * LDIM; i += NTHREADS) {      // B2[n][k] = W2[k][n]
        int k = i / LDIM, n = i - k * LDIM;
        uint16_t h, l; split1(W2[i], h, l);
        *(uint16_t*)(sm + OFF_B2H + n * P192 + k * 2) = h;
        *(uint16_t*)(sm + OFF_B2L + n * P192 + k * 2) = l;
    }
    if (tid < 96) { GAM[tid] = gamma[tid]; BET[tid] = beta[tid]; }
    __syncthreads();

    // ---- prologue: stage first X tile (128 x 96) ----
    if (blockIdx.x < ntiles) {
        const float4* xg = (const float4*)(x + (size_t)blockIdx.x * (TILE_R * LDIM));
        #pragma unroll
        for (int it = 0; it < 12; ++it) {
            int i4 = tid + it * NTHREADS;
            float4 v = xg[i4];
            int e = i4 * 4, r = e / LDIM, c = e - LDIM * r;
            *(uint32_t*)(sm + OFF_XH + r * P96 + c * 2)     = pack2(h16(v.x), h16(v.y));
            *(uint32_t*)(sm + OFF_XH + r * P96 + c * 2 + 4) = pack2(h16(v.z), h16(v.w));
        }
    }
    __syncthreads();

    for (int tile = blockIdx.x; tile < ntiles; tile += gridDim.x) {
        const size_t rowbase = (size_t)tile * TILE_R;

        // ---- 0) prefetch next tile's X, convert to packed fp16 immediately ----
        const int ntile = tile + gridDim.x;
        const bool havepf = ntile < ntiles;
        uint32_t pfu[24];
        if (havepf) {
            const float4* xg = (const float4*)(x + (size_t)ntile * (TILE_R * LDIM));
            #pragma unroll
            for (int it = 0; it < 12; ++it) {
                float4 v = xg[tid + it * NTHREADS];
                pfu[it * 2]     = pack2(h16(v.x), h16(v.y));
                pfu[it * 2 + 1] = pack2(h16(v.z), h16(v.w));
            }
        }

        // ---- 1) GEMM1: D1(128x192) = Xh @ (B1h + B1l); 4 m-blocks x 6 j ----
        float acc1[4][6][4];
        #pragma unroll
        for (int mb = 0; mb < 4; ++mb)
            #pragma unroll
            for (int j = 0; j < 6; ++j)
                #pragma unroll
                for (int p = 0; p < 4; ++p) acc1[mb][j][p] = 0.f;

        #pragma unroll
        for (int ks = 0; ks < 6; ++ks) {
            uint32_t a[4][4];
            #pragma unroll
            for (int mb = 0; mb < 4; ++mb) {
                int ab = (mh * 64 + mb * 16 + g) * P96 + ks * 32 + 4 * t;
                a[mb][0] = *(const uint32_t*)(sm + OFF_XH + ab);
                a[mb][1] = *(const uint32_t*)(sm + OFF_XH + ab + 8 * P96);
                a[mb][2] = *(const uint32_t*)(sm + OFF_XH + ab + 16);
                a[mb][3] = *(const uint32_t*)(sm + OFF_XH + ab + 8 * P96 + 16);
            }
            #pragma unroll
            for (int j = 0; j < 6; ++j) {
                int bbyte = ((nq * 6 + j) * 8 + g) * P96 + ks * 32 + 4 * t;
                uint32_t bh0 = *(const uint32_t*)(sm + OFF_B1H + bbyte);
                uint32_t bh1 = *(const uint32_t*)(sm + OFF_B1H + bbyte + 16);
                uint32_t bl0 = *(const uint32_t*)(sm + OFF_B1L + bbyte);
                uint32_t bl1 = *(const uint32_t*)(sm + OFF_B1L + bbyte + 16);
                #pragma unroll
                for (int mb = 0; mb < 4; ++mb) {
                    mma_f16(acc1[mb][j], a[mb][0], a[mb][1], a[mb][2], a[mb][3], bh0, bh1);
                    mma_f16(acc1[mb][j], a[mb][0], a[mb][1], a[mb][2], a[mb][3], bl0, bl1);
                }
            }
        }
        __syncthreads();   // X reads done -> region becomes H

        // ---- 2) relu -> H hi (fp16) in smem ----
        #pragma unroll
        for (int mb = 0; mb < 4; ++mb) {
            int M0 = mh * 64 + mb * 16;
            #pragma unroll
            for (int j = 0; j < 6; ++j) {
                int N0 = (nq * 6 + j) * 8;
                float c0 = fmaxf(acc1[mb][j][0], 0.f), c1 = fmaxf(acc1[mb][j][1], 0.f);
                float c2 = fmaxf(acc1[mb][j][2], 0.f), c3 = fmaxf(acc1[mb][j][3], 0.f);
                int b0 = (M0 + g) * P192 + (N0 + 2 * t) * 2;
                int b1 = (M0 + g + 8) * P192 + (N0 + 2 * t) * 2;
                *(uint32_t*)(sm + OFF_HH + b0) = pack2(h16(c0), h16(c1));
                *(uint32_t*)(sm + OFF_HH + b1) = pack2(h16(c2), h16(c3));
            }
        }
        __syncthreads();

        // ---- 3) GEMM2: D2(128x96) = Hh @ (B2h + B2l); 4 m-blocks x 3 j ----
        float acc2[4][3][4];
        #pragma unroll
        for (int mb = 0; mb < 4; ++mb)
            #pragma unroll
            for (int j = 0; j < 3; ++j)
                #pragma unroll
                for (int p = 0; p < 4; ++p) acc2[mb][j][p] = 0.f;

        #pragma unroll
        for (int ks = 0; ks < 12; ++ks) {
            uint32_t a[4][4];
            #pragma unroll
            for (int mb = 0; mb < 4; ++mb) {
                int ab = (mh * 64 + mb * 16 + g) * P192 + ks * 32 + 4 * t;
                a[mb][0] = *(const uint32_t*)(sm + OFF_HH + ab);
                a[mb][1] = *(const uint32_t*)(sm + OFF_HH + ab + 8 * P192);
                a[mb][2] = *(const uint32_t*)(sm + OFF_HH + ab + 16);
                a[mb][3] = *(const uint32_t*)(sm + OFF_HH + ab + 8 * P192 + 16);
            }
            #pragma unroll
            for (int j = 0; j < 3; ++j) {
                int bbyte = ((nq * 3 + j) * 8 + g) * P192 + ks * 32 + 4 * t;
                uint32_t bh0 = *(const uint32_t*)(sm + OFF_B2H + bbyte);
                uint32_t bh1 = *(const uint32_t*)(sm + OFF_B2H + bbyte + 16);
                uint32_t bl0 = *(const uint32_t*)(sm + OFF_B2L + bbyte);
                uint32_t bl1 = *(const uint32_t*)(sm + OFF_B2L + bbyte + 16);
                #pragma unroll
                for (int mb = 0; mb < 4; ++mb) {
                    mma_f16(acc2[mb][j], a[mb][0], a[mb][1], a[mb][2], a[mb][3], bh0, bh1);
                    mma_f16(acc2[mb][j], a[mb][0], a[mb][1], a[mb][2], a[mb][3], bl0, bl1);
                }
            }
        }

        // ---- 4) sigmoid + LayerNorm + x*lr ----
        {
            // 8 rows per warp: for mb: r = mh*64 + mb*16 + g (+8)
            float v[4][3][4];
            float p[8] = {0.f, 0.f, 0.f, 0.f, 0.f, 0.f, 0.f, 0.f};
            #pragma unroll
            for (int mb = 0; mb < 4; ++mb)
                #pragma unroll
                for (int j = 0; j < 3; ++j) {
                    #pragma unroll
                    for (int q2 = 0; q2 < 4; ++q2)
                        v[mb][j][q2] = __fdividef(1.f, 1.f + __expf(-acc2[mb][j][q2]));
                    p[mb * 2]     += v[mb][j][0] + v[mb][j][1];
                    p[mb * 2 + 1] += v[mb][j][2] + v[mb][j][3];
                }
            #pragma unroll
            for (int r = 0; r < 8; ++r) {
                p[r] += __shfl_xor_sync(0xffffffffu, p[r], 1);
                p[r] += __shfl_xor_sync(0xffffffffu, p[r], 2);
            }
            int rows[8];
            #pragma unroll
            for (int mb = 0; mb < 4; ++mb) {
                rows[mb * 2]     = mh * 64 + mb * 16 + g;
                rows[mb * 2 + 1] = mh * 64 + mb * 16 + g + 8;
            }
            if (t == 0) {
                #pragma unroll
                for (int r = 0; r < 8; ++r) S[nq * 128 + rows[r]] = p[r];
            }
            __syncthreads();
            float mu[8];
            #pragma unroll
            for (int r = 0; r < 8; ++r)
                mu[r] = (S[rows[r]] + S[128 + rows[r]] + S[256 + rows[r]] + S[384 + rows[r]])
                        * (1.f / 96.f);

            float q[8] = {0.f, 0.f, 0.f, 0.f, 0.f, 0.f, 0.f, 0.f};
            #pragma unroll
            for (int mb = 0; mb < 4; ++mb)
                #pragma unroll
                for (int j = 0; j < 3; ++j) {
                    float d0 = v[mb][j][0] - mu[mb * 2],     d1 = v[mb][j][1] - mu[mb * 2];
                    float d2 = v[mb][j][2] - mu[mb * 2 + 1], d3 = v[mb][j][3] - mu[mb * 2 + 1];
                    q[mb * 2]     += d0 * d0 + d1 * d1;
                    q[mb * 2 + 1] += d2 * d2 + d3 * d3;
                }
            #pragma unroll
            for (int r = 0; r < 8; ++r) {
                q[r] += __shfl_xor_sync(0xffffffffu, q[r], 1);
                q[r] += __shfl_xor_sync(0xffffffffu, q[r], 2);
            }
            if (t == 0) {
                #pragma unroll
                for (int r = 0; r < 8; ++r) Q[nq * 128 + rows[r]] = q[r];
            }
            __syncthreads();   // after this, ALL warps' GEMM2 (H reads) are done
            float inv[8];
            #pragma unroll
            for (int r = 0; r < 8; ++r)
                inv[r] = rsqrtf((Q[rows[r]] + Q[128 + rows[r]] + Q[256 + rows[r]] + Q[384 + rows[r]])
                                * (1.f / 96.f) + 1e-6f);

            #pragma unroll
            for (int mb = 0; mb < 4; ++mb)
                #pragma unroll
                for (int j = 0; j < 3; ++j) {
                    int col = (nq * 3 + j) * 8 + 2 * t;
                    float2 gmv = *(const float2*)&GAM[col];
                    float2 btv = *(const float2*)&BET[col];
                    int ra = rows[mb * 2], rb = rows[mb * 2 + 1];
                    float2 xva = *(const float2*)(x + (rowbase + ra) * LDIM + col);
                    float2 xvb = *(const float2*)(x + (rowbase + rb) * LDIM + col);
                    float2 oa, ob;
                    oa.x = xva.x * ((v[mb][j][0] - mu[mb * 2]) * inv[mb * 2] * gmv.x + btv.x);
                    oa.y = xva.y * ((v[mb][j][1] - mu[mb * 2]) * inv[mb * 2] * gmv.y + btv.y);
                    ob.x = xvb.x * ((v[mb][j][2] - mu[mb * 2 + 1]) * inv[mb * 2 + 1] * gmv.x + btv.x);
                    ob.y = xvb.y * ((v[mb][j][3] - mu[mb * 2 + 1]) * inv[mb * 2 + 1] * gmv.y + btv.y);
                    *(float2*)(out + (rowbase + ra) * LDIM + col) = oa;
                    *(float2*)(out + (rowbase + rb) * LDIM + col) = ob;
                }
        }

        // ---- 5) store prefetched X(t+1) over H (all H reads done at Q-barrier) ----
        if (havepf) {
            #pragma unroll
            for (int it = 0; it < 12; ++it) {
                int i4 = tid + it * NTHREADS;
                int e = i4 * 4, r = e / LDIM, c = e - LDIM * r;
                *(uint32_t*)(sm + OFF_XH + r * P96 + c * 2)     = pfu[it * 2];
                *(uint32_t*)(sm + OFF_XH + r * P96 + c * 2 + 4) = pfu[it * 2 + 1];
            }
        }
        __syncthreads();   // X(t+1) staged before next GEMM1
    }
}

extern "C" void kernel_launch(void* const* d_in, const int* in_sizes, int n_in,
                              void* d_out, int out_size) {
    const float* x     = (const float*)d_in[0];
    const float* W1    = (const float*)d_in[1];
    const float* W2    = (const float*)d_in[2];
    const float* gamma = (const float*)d_in[3];
    const float* beta  = (const float*)d_in[4];
    float* out = (float*)d_out;

    int rows   = in_sizes[0] / LDIM;     // 786432
    int ntiles = rows / TILE_R;          // 6144

    precompute_m1_kernel<<<LDIM, FDIM>>>(W1);

    cudaFuncSetAttribute(fused_mma_kernel,
                         cudaFuncAttributeMaxDynamicSharedMemorySize, SMEM_BYTES);

    int nsm = 148;
    cudaDeviceGetAttribute(&nsm, cudaDevAttrMultiProcessorCount, 0);
    int grid = nsm < ntiles ? nsm : ntiles;

    fused_mma_kernel<<<grid, NTHREADS, SMEM_BYTES>>>(x, W2, gamma, beta, out, ntiles);
}